// round 14
// baseline (speedup 1.0000x reference)
#include <cuda_runtime.h>
#include <math.h>
#include <stdint.h>

// Problem constants
#define B 8
#define A 100000
#define M 32
#define C 80
#define APB 320                      // threads = anchors per tile (16*20)
#define NTILES ((A + APB - 1) / APB) // 313
#define NBLK (NTILES * B)            // 2504
#define V4PA (C / 4)                 // float4 per anchor = 20
#define CHA 80                       // anchors per chunk
#define CHF (CHA * C)                // 6400 floats per chunk
#define CHB (CHF * 4)                // 25600 bytes per chunk
#define NCH 4                        // chunks per full tile
#define SMEM_DYN (NCH * CHB)         // 102400 bytes: whole tile resident

// mask weight for contributing anchors: -0.75 * ln(2)
#define NEGW (-0.5198603854199589f)

// Per-CTA partials + finalize ticket (device globals; no allocation allowed)
__device__ float g_cls_part[NBLK];
__device__ float g_reg_part[NBLK];
__device__ int   g_pos_part[NBLK];
__device__ unsigned int g_ticket = 0;

__device__ __forceinline__ uint32_t s2u(const void* p) {
    uint32_t r;
    asm("{ .reg .u64 t; cvta.to.shared.u64 t, %1; cvt.u32.u64 %0, t; }"
        : "=r"(r) : "l"(p));
    return r;
}
__device__ __forceinline__ void mbar_init(uint32_t mbar, uint32_t cnt) {
    asm volatile("mbarrier.init.shared.b64 [%0], %1;" :: "r"(mbar), "r"(cnt) : "memory");
}
__device__ __forceinline__ void mbar_expect_tx(uint32_t mbar, uint32_t bytes) {
    asm volatile("mbarrier.arrive.expect_tx.shared.b64 _, [%0], %1;"
                 :: "r"(mbar), "r"(bytes) : "memory");
}
__device__ __forceinline__ void bulk_g2s(uint32_t dst, const void* src,
                                         uint32_t bytes, uint32_t mbar) {
    asm volatile(
        "cp.async.bulk.shared::cta.global.mbarrier::complete_tx::bytes "
        "[%0], [%1], %2, [%3];"
        :: "r"(dst), "l"(src), "r"(bytes), "r"(mbar) : "memory");
}
__device__ __forceinline__ void mbar_wait(uint32_t mbar, uint32_t parity) {
    asm volatile(
        "{\n\t"
        ".reg .pred P;\n\t"
        "WL_%=:\n\t"
        "mbarrier.try_wait.parity.acquire.cta.shared::cta.b64 P, [%0], %1, 0x989680;\n\t"
        "@P bra WD_%=;\n\t"
        "bra WL_%=;\n\t"
        "WD_%=:\n\t"
        "}"
        :: "r"(mbar), "r"(parity) : "memory");
}

__global__ __launch_bounds__(APB) void fl_tile_kernel(
    const float* __restrict__ cls,      // [B, A, C]
    const float* __restrict__ reg,      // [B, A, 4]
    const float* __restrict__ anchors,  // [1, A, 4]
    const float* __restrict__ ann,      // [B, M, 6]
    float* __restrict__ out)            // [2]
{
    extern __shared__ __align__(16) float s_buf[];   // NCH stages x CHF floats

    __shared__ float4 s_box[M];
    __shared__ float2 s_misc[M];         // x = area_b, y = class id
    __shared__ float  s_mask[APB];       // NEGW if anchor contributes, else 0
    __shared__ float  s_rc[APB / 32];
    __shared__ float  s_rr[APB / 32];
    __shared__ int    s_rp[APB / 32];
    __shared__ bool   s_last;
    __shared__ __align__(8) unsigned long long s_mbar[NCH];

    const int b    = blockIdx.y;
    const int a0   = blockIdx.x * APB;
    const int tid  = threadIdx.x;
    const int wid  = tid >> 5;
    const int lane = tid & 31;
    const int blk  = b * NTILES + blockIdx.x;
    const int nA   = min(APB, A - a0);      // 320 or 160 (both multiples of 80)
    const int nchunks = nA / CHA;           // 4 or 2

    const float* __restrict__ tile = cls + ((size_t)b * A + a0) * C;

    // init mbarriers + stage annotations
    if (tid < NCH) mbar_init(s2u(&s_mbar[tid]), 1);
    if (tid < M) {
        const float* ap = ann + (b * M + tid) * 6;
        float x1 = ap[0], y1 = ap[1], x2 = ap[2], y2 = ap[3];
        const float cl = ap[4];
        float area = (x2 - x1) * (y2 - y1);
        if (cl == -1.0f) {
            // Invalid GT: far-away box -> inter == 0 always, area 0 ->
            // identical classification/argmax behavior to reference's iou=-1.
            x1 = 3e9f; y1 = 3e9f; x2 = 3e9f; y2 = 3e9f; area = 0.0f;
        }
        s_box[tid]  = make_float4(x1, y1, x2, y2);
        s_misc[tid] = make_float2(area, cl);
    }
    __syncthreads();

    // ---- issue ALL chunks upfront: the copy engine keeps up to 100KB/CTA
    // in flight with zero registers and zero further issue slots. ----
    if (tid == 0) {
        #pragma unroll
        for (int k = 0; k < NCH; k++) {
            if (k < nchunks) {
                const uint32_t mb = s2u(&s_mbar[k]);
                mbar_expect_tx(mb, CHB);
                bulk_g2s(s2u(&s_buf[k * CHF]), tile + k * CHF, CHB, mb);
            }
        }
    }

    // ================= phase 1: IoU assignment (overlapped with copies) ====
    float cls_partial = 0.0f;
    float reg_partial = 0.0f;
    int   pos_cnt = 0;

    const int a = a0 + tid;
    if (a < A) {
        const float4 av = *reinterpret_cast<const float4*>(anchors + a * 4);
        const float ax1 = av.x, ay1 = av.y, ax2 = av.z, ay2 = av.w;
        const float aw = ax2 - ax1;
        const float ah = ay2 - ay1;
        const float area_a = aw * ah;

        // IoU argmax via cross-multiplication (no division; ua >= area_a > 0)
        float b_in = -1.0f, b_ua = 1.0f;
        int   bi = 0;
        #pragma unroll 8
        for (int j = 0; j < M; j++) {
            const float4 g  = s_box[j];
            const float2 mi = s_misc[j];
            const float iw = fminf(ax2, g.z) - fmaxf(ax1, g.x);
            const float ih = fminf(ay2, g.w) - fmaxf(ay1, g.y);
            const float inter = fmaxf(iw, 0.0f) * fmaxf(ih, 0.0f);
            const float ua = (area_a + mi.x) - inter;
            if (inter * b_ua > b_in * ua) { b_in = inter; b_ua = ua; bi = j; }
        }

        const bool pos = (b_in >= 0.5f * b_ua);
        const bool ign = (!pos) && (b_in >= 0.4f * b_ua);
        s_mask[tid] = ign ? 0.0f : NEGW;

        if (pos) {
            pos_cnt = 1;
            const float4 g = s_box[bi];

            // positive-class correction: remove exactly the unmasked sweep
            // term, add the reference positive term.
            const int cid = (int)s_misc[bi].y;
            const float p_raw = cls[((size_t)b * A + a) * C + cid];
            const float sweep_term =
                NEGW * (p_raw * p_raw * __log2f(1.0f - p_raw));
            const float pc = fminf(fmaxf(p_raw, 1e-4f), 1.0f - 1e-4f);
            const float qc = 1.0f - pc;
            cls_partial += 0.25f * qc * qc * (-__logf(pc)) - sweep_term;

            // regression loss (smooth L1)
            float gw = g.z - g.x;
            float gh = g.w - g.y;
            const float gcx = g.x + 0.5f * gw;
            const float gcy = g.y + 0.5f * gh;
            gw = fmaxf(gw, 1.0f);
            gh = fmaxf(gh, 1.0f);
            const float acx = ax1 + 0.5f * aw;
            const float acy = ay1 + 0.5f * ah;
            const float t0 = ((gcx - acx) / aw) * 10.0f;
            const float t1 = ((gcy - acy) / ah) * 10.0f;
            const float t2 = __logf(gw / aw) * 5.0f;
            const float t3 = __logf(gh / ah) * 5.0f;
            const float4 r = *reinterpret_cast<const float4*>(reg + ((size_t)b * A + a) * 4);
            const float d0 = fabsf(t0 - r.x);
            const float d1 = fabsf(t1 - r.y);
            const float d2 = fabsf(t2 - r.z);
            const float d3 = fabsf(t3 - r.w);
            const float th = 1.0f / 9.0f;
            const float c2 = 0.5f / 9.0f;
            reg_partial  = (d0 <= th) ? 4.5f * d0 * d0 : d0 - c2;
            reg_partial += (d1 <= th) ? 4.5f * d1 * d1 : d1 - c2;
            reg_partial += (d2 <= th) ? 4.5f * d2 * d2 : d2 - c2;
            reg_partial += (d3 <= th) ? 4.5f * d3 * d3 : d3 - c2;
        }
    } else {
        s_mask[tid] = 0.0f;
    }
    __syncthreads();   // masks visible to all consumers

    // ================= phase 2: consume resident chunks ====================
    // No re-issue, no mid-loop syncthreads: just wait each chunk's mbarrier
    // (parity 0, single use) and burn through it from shared memory.
    const int mbase = tid / 20;   // APB = 16*20: anchor(tid+320j) = mbase+16j
    float acc0 = 0.f, acc1 = 0.f;

    #pragma unroll
    for (int k = 0; k < NCH; k++) {
        if (k >= nchunks) break;
        mbar_wait(s2u(&s_mbar[k]), 0);
        const float4* sb4 = reinterpret_cast<const float4*>(s_buf + k * CHF);
        const int moff = k * CHA;
        #pragma unroll
        for (int j = 0; j < 5; j++) {
            const float4 v = sb4[tid + j * APB];
            const float m = s_mask[moff + mbase + 16 * j];
            const float l0 = __log2f(1.0f - v.x);
            const float l1 = __log2f(1.0f - v.y);
            const float l2 = __log2f(1.0f - v.z);
            const float l3 = __log2f(1.0f - v.w);
            const float s = fmaf(v.x * v.x, l0, fmaf(v.y * v.y, l1,
                            fmaf(v.z * v.z, l2, (v.w * v.w) * l3)));
            if (j & 1) acc1 = fmaf(m, s, acc1);
            else       acc0 = fmaf(m, s, acc0);
        }
    }
    cls_partial += acc0 + acc1;

    // Block reduction -> per-CTA partials
    float cv = cls_partial;
    float rv = reg_partial;
    int   pv = pos_cnt;
    #pragma unroll
    for (int o = 16; o > 0; o >>= 1) {
        cv += __shfl_down_sync(0xFFFFFFFFu, cv, o);
        rv += __shfl_down_sync(0xFFFFFFFFu, rv, o);
        pv += __shfl_down_sync(0xFFFFFFFFu, pv, o);
    }
    if (lane == 0) { s_rc[wid] = cv; s_rr[wid] = rv; s_rp[wid] = pv; }
    __syncthreads();

    if (tid == 0) {
        float c = 0.0f, r = 0.0f;
        int p = 0;
        #pragma unroll
        for (int i = 0; i < APB / 32; i++) { c += s_rc[i]; r += s_rr[i]; p += s_rp[i]; }
        g_cls_part[blk] = c;
        g_reg_part[blk] = r;
        g_pos_part[blk] = p;
        __threadfence();
        const unsigned int t = atomicAdd(&g_ticket, 1u);
        s_last = (t == (unsigned int)(NBLK - 1));
    }
    __syncthreads();

    // Last CTA reduces all per-CTA partials and writes the output.
    if (s_last) {
        __shared__ double f_c[B][APB / 32];
        __shared__ double f_r[B][APB / 32];
        __shared__ int    f_p[B][APB / 32];

        #pragma unroll
        for (int img = 0; img < B; img++) {
            double c = 0.0, r = 0.0;
            int p = 0;
            for (int i = tid; i < NTILES; i += APB) {
                const int idx = img * NTILES + i;
                c += (double)g_cls_part[idx];
                r += (double)g_reg_part[idx];
                p += g_pos_part[idx];
            }
            #pragma unroll
            for (int o = 16; o > 0; o >>= 1) {
                c += __shfl_down_sync(0xFFFFFFFFu, c, o);
                r += __shfl_down_sync(0xFFFFFFFFu, r, o);
                p += __shfl_down_sync(0xFFFFFFFFu, p, o);
            }
            if (lane == 0) { f_c[img][wid] = c; f_r[img][wid] = r; f_p[img][wid] = p; }
        }
        __syncthreads();
        if (tid == 0) {
            double cl = 0.0, rl = 0.0;
            #pragma unroll
            for (int img = 0; img < B; img++) {
                double c = 0.0, r = 0.0;
                int p = 0;
                #pragma unroll
                for (int i = 0; i < APB / 32; i++) {
                    c += f_c[img][i]; r += f_r[img][i]; p += f_p[img][i];
                }
                const double d = (p < 1) ? 1.0 : (double)p;
                cl += c / d;
                if (p > 0) rl += r / (4.0 * d);
            }
            out[0] = (float)(cl / (double)B);
            out[1] = (float)(rl / (double)B);
            g_ticket = 0;  // reset for the next graph replay
        }
    }
}

extern "C" void kernel_launch(void* const* d_in, const int* in_sizes, int n_in,
                              void* d_out, int out_size) {
    const float* cls = nullptr;
    const float* reg = nullptr;
    const float* anc = nullptr;
    const float* ann = nullptr;
    for (int i = 0; i < n_in; i++) {
        switch (in_sizes[i]) {
            case B * A * C:  cls = (const float*)d_in[i]; break;  // 64,000,000
            case B * A * 4:  reg = (const float*)d_in[i]; break;  //  3,200,000
            case A * 4:      anc = (const float*)d_in[i]; break;  //    400,000
            case B * M * 6:  ann = (const float*)d_in[i]; break;  //      1,536
            default: break;
        }
    }
    float* out = (float*)d_out;

    cudaFuncSetAttribute(fl_tile_kernel,
                         cudaFuncAttributeMaxDynamicSharedMemorySize, SMEM_DYN);
    dim3 grid(NTILES, B);
    fl_tile_kernel<<<grid, APB, SMEM_DYN>>>(cls, reg, anc, ann, out);
}

// round 15
// speedup vs baseline: 1.0262x; 1.0262x over previous
#include <cuda_runtime.h>
#include <math.h>
#include <stdint.h>

// Problem constants
#define B 8
#define A 100000
#define M 32
#define C 80
#define APB 320                      // threads = anchors per tile (16*20)
#define NTILES ((A + APB - 1) / APB) // 313
#define NBLK (NTILES * B)            // 2504 tiles
#define GRID 592                     // 4 persistent CTAs per SM x 148
#define V4PA (C / 4)                 // float4 per anchor = 20
#define CHA 80                       // anchors per chunk
#define CHF (CHA * C)                // 6400 floats per chunk
#define CHB (CHF * 4)                // 25600 bytes per chunk
#define SMEM_DYN (2 * CHB)           // 51200 bytes (double buffer ring)

// mask weight for contributing anchors: -0.75 * ln(2)
#define NEGW (-0.5198603854199589f)

// Per-tile partials + finalize ticket (device globals; no allocation allowed)
__device__ float g_cls_part[NBLK];
__device__ float g_reg_part[NBLK];
__device__ int   g_pos_part[NBLK];
__device__ unsigned int g_ticket = 0;

__device__ __forceinline__ uint32_t s2u(const void* p) {
    uint32_t r;
    asm("{ .reg .u64 t; cvta.to.shared.u64 t, %1; cvt.u32.u64 %0, t; }"
        : "=r"(r) : "l"(p));
    return r;
}
__device__ __forceinline__ void mbar_init(uint32_t mbar, uint32_t cnt) {
    asm volatile("mbarrier.init.shared.b64 [%0], %1;" :: "r"(mbar), "r"(cnt) : "memory");
}
__device__ __forceinline__ void mbar_expect_tx(uint32_t mbar, uint32_t bytes) {
    asm volatile("mbarrier.arrive.expect_tx.shared.b64 _, [%0], %1;"
                 :: "r"(mbar), "r"(bytes) : "memory");
}
__device__ __forceinline__ void bulk_g2s(uint32_t dst, const void* src,
                                         uint32_t bytes, uint32_t mbar) {
    asm volatile(
        "cp.async.bulk.shared::cta.global.mbarrier::complete_tx::bytes "
        "[%0], [%1], %2, [%3];"
        :: "r"(dst), "l"(src), "r"(bytes), "r"(mbar) : "memory");
}
__device__ __forceinline__ void fence_async_shared() {
    asm volatile("fence.proxy.async.shared::cta;" ::: "memory");
}
__device__ __forceinline__ void mbar_wait(uint32_t mbar, uint32_t parity) {
    asm volatile(
        "{\n\t"
        ".reg .pred P;\n\t"
        "WL_%=:\n\t"
        "mbarrier.try_wait.parity.acquire.cta.shared::cta.b64 P, [%0], %1, 0x989680;\n\t"
        "@P bra WD_%=;\n\t"
        "bra WL_%=;\n\t"
        "WD_%=:\n\t"
        "}"
        :: "r"(mbar), "r"(parity) : "memory");
}

// chunks in tile t: edge column (tx == NTILES-1) has 160 anchors -> 2 chunks
__device__ __forceinline__ int tile_nch(int t) {
    return ((t % NTILES) == NTILES - 1) ? 2 : 4;
}

__global__ __launch_bounds__(APB, 4) void fl_ring_kernel(
    const float* __restrict__ cls,      // [B, A, C]
    const float* __restrict__ reg,      // [B, A, 4]
    const float* __restrict__ anchors,  // [1, A, 4]
    const float* __restrict__ ann,      // [B, M, 6]
    float* __restrict__ out)            // [2]
{
    extern __shared__ __align__(16) float s_buf[];   // 2 stages x CHF floats

    __shared__ float4 s_box[M];
    __shared__ float2 s_misc[M];         // x = area_b, y = class id
    __shared__ float  s_mask[APB];       // per-tile masks
    __shared__ float  s_rc[APB / 32];
    __shared__ float  s_rr[APB / 32];
    __shared__ int    s_rp[APB / 32];
    __shared__ bool   s_final;
    __shared__ __align__(8) unsigned long long s_mbar[2];

    const int tid  = threadIdx.x;
    const int wid  = tid >> 5;
    const int lane = tid & 31;
    const int bid  = blockIdx.x;

    const uint32_t mb[2] = { s2u(&s_mbar[0]), s2u(&s_mbar[1]) };
    const uint32_t sb[2] = { s2u(&s_buf[0]),  s2u(&s_buf[CHF]) };

    if (tid == 0) {
        mbar_init(mb[0], 1);
        mbar_init(mb[1], 1);
        s_final = false;
    }
    __syncthreads();

    // ---- issue cursor (uniform across threads; only tid0 acts) ----
    int it_t = bid;      // tile being issued
    int it_c = 0;        // next chunk within it_t
    int q_issue = 0;     // chunks issued so far (ring slot = q_issue & 1)
    int q_cons  = 0;     // chunks consumed so far

    // prologue: put 2 chunks in flight before any compute
    #pragma unroll
    for (int i = 0; i < 2; i++) {
        if (it_t < NBLK) {
            if (tid == 0) {
                const int ib = it_t / NTILES, ix = it_t % NTILES;
                const float* src = cls + ((size_t)ib * A + ix * APB + it_c * CHA) * C;
                mbar_expect_tx(mb[q_issue & 1], CHB);
                bulk_g2s(sb[q_issue & 1], src, CHB, mb[q_issue & 1]);
            }
            q_issue++;
            if (++it_c == tile_nch(it_t)) { it_c = 0; it_t += GRID; }
        }
    }

    // =================== persistent tile loop ===================
    for (int t = bid; t < NBLK; t += GRID) {
        const int b  = t / NTILES;
        const int tx = t % NTILES;
        const int a0 = tx * APB;
        const int nch = tile_nch(t);

        // stage annotations for image b (safe: previous tile's consumers all
        // passed the post-consume syncthreads before we get here)
        if (tid < M) {
            const float* ap = ann + (b * M + tid) * 6;
            float x1 = ap[0], y1 = ap[1], x2 = ap[2], y2 = ap[3];
            const float cl = ap[4];
            float area = (x2 - x1) * (y2 - y1);
            if (cl == -1.0f) {
                // Invalid GT: far-away box -> inter == 0 always, area 0 ->
                // identical classification/argmax behavior to iou = -1.
                x1 = 3e9f; y1 = 3e9f; x2 = 3e9f; y2 = 3e9f; area = 0.0f;
            }
            s_box[tid]  = make_float4(x1, y1, x2, y2);
            s_misc[tid] = make_float2(area, cl);
        }
        __syncthreads();

        // ---- phase 1: IoU assignment (overlaps in-flight bulk copies) ----
        float cls_partial = 0.0f;
        float reg_partial = 0.0f;
        int   pos_cnt = 0;

        const int a = a0 + tid;
        if (a < A) {
            const float4 av = *reinterpret_cast<const float4*>(anchors + a * 4);
            const float ax1 = av.x, ay1 = av.y, ax2 = av.z, ay2 = av.w;
            const float aw = ax2 - ax1;
            const float ah = ay2 - ay1;
            const float area_a = aw * ah;

            float b_in = -1.0f, b_ua = 1.0f;
            int   bi = 0;
            #pragma unroll 8
            for (int j = 0; j < M; j++) {
                const float4 g  = s_box[j];
                const float2 mi = s_misc[j];
                const float iw = fminf(ax2, g.z) - fmaxf(ax1, g.x);
                const float ih = fminf(ay2, g.w) - fmaxf(ay1, g.y);
                const float inter = fmaxf(iw, 0.0f) * fmaxf(ih, 0.0f);
                const float ua = (area_a + mi.x) - inter;
                if (inter * b_ua > b_in * ua) { b_in = inter; b_ua = ua; bi = j; }
            }

            const bool pos = (b_in >= 0.5f * b_ua);
            const bool ign = (!pos) && (b_in >= 0.4f * b_ua);
            s_mask[tid] = ign ? 0.0f : NEGW;

            if (pos) {
                pos_cnt = 1;
                const float4 g = s_box[bi];

                // positive-class correction (remove unmasked sweep term,
                // add reference positive term)
                const int cid = (int)s_misc[bi].y;
                const float p_raw = cls[((size_t)b * A + a) * C + cid];
                const float sweep_term =
                    NEGW * (p_raw * p_raw * __log2f(1.0f - p_raw));
                const float pc = fminf(fmaxf(p_raw, 1e-4f), 1.0f - 1e-4f);
                const float qc = 1.0f - pc;
                cls_partial += 0.25f * qc * qc * (-__logf(pc)) - sweep_term;

                // regression loss (smooth L1)
                float gw = g.z - g.x;
                float gh = g.w - g.y;
                const float gcx = g.x + 0.5f * gw;
                const float gcy = g.y + 0.5f * gh;
                gw = fmaxf(gw, 1.0f);
                gh = fmaxf(gh, 1.0f);
                const float acx = ax1 + 0.5f * aw;
                const float acy = ay1 + 0.5f * ah;
                const float t0 = ((gcx - acx) / aw) * 10.0f;
                const float t1 = ((gcy - acy) / ah) * 10.0f;
                const float t2 = __logf(gw / aw) * 5.0f;
                const float t3 = __logf(gh / ah) * 5.0f;
                const float4 r = *reinterpret_cast<const float4*>(
                    reg + ((size_t)b * A + a) * 4);
                const float d0 = fabsf(t0 - r.x);
                const float d1 = fabsf(t1 - r.y);
                const float d2 = fabsf(t2 - r.z);
                const float d3 = fabsf(t3 - r.w);
                const float th = 1.0f / 9.0f;
                const float c2 = 0.5f / 9.0f;
                reg_partial  = (d0 <= th) ? 4.5f * d0 * d0 : d0 - c2;
                reg_partial += (d1 <= th) ? 4.5f * d1 * d1 : d1 - c2;
                reg_partial += (d2 <= th) ? 4.5f * d2 * d2 : d2 - c2;
                reg_partial += (d3 <= th) ? 4.5f * d3 * d3 : d3 - c2;
            }
        } else {
            s_mask[tid] = 0.0f;
        }
        __syncthreads();   // masks visible

        // ---- phase 2: ring consume; re-issue keeps the stream continuous
        // across tile boundaries (next tile's chunks load during this tile's
        // consume; next phase 1 runs with 51.2KB already in flight) ----
        const int mbase = tid / 20;
        float acc0 = 0.f, acc1 = 0.f;

        for (int c = 0; c < nch; c++) {
            const int slot = q_cons & 1;
            mbar_wait(mb[slot], (q_cons >> 1) & 1);
            q_cons++;

            const float4* sb4 = reinterpret_cast<const float4*>(
                s_buf + slot * CHF);
            const int moff = c * CHA;
            #pragma unroll
            for (int j = 0; j < 5; j++) {
                const float4 v = sb4[tid + j * APB];
                const float m = s_mask[moff + mbase + 16 * j];
                const float l0 = __log2f(1.0f - v.x);
                const float l1 = __log2f(1.0f - v.y);
                const float l2 = __log2f(1.0f - v.z);
                const float l3 = __log2f(1.0f - v.w);
                const float s = fmaf(v.x * v.x, l0, fmaf(v.y * v.y, l1,
                                fmaf(v.z * v.z, l2, (v.w * v.w) * l3)));
                if (j & 1) acc1 = fmaf(m, s, acc1);
                else       acc0 = fmaf(m, s, acc0);
            }

            __syncthreads();   // all reads of this slot done
            if (it_t < NBLK) {
                if (tid == 0) {
                    fence_async_shared();
                    const int ib = it_t / NTILES, ix = it_t % NTILES;
                    const float* src = cls +
                        ((size_t)ib * A + ix * APB + it_c * CHA) * C;
                    mbar_expect_tx(mb[q_issue & 1], CHB);
                    bulk_g2s(sb[q_issue & 1], src, CHB, mb[q_issue & 1]);
                }
                q_issue++;
                if (++it_c == tile_nch(it_t)) { it_c = 0; it_t += GRID; }
            }
        }
        cls_partial += acc0 + acc1;

        // ---- per-tile block reduction -> global partials + ticket ----
        float cv = cls_partial;
        float rv = reg_partial;
        int   pv = pos_cnt;
        #pragma unroll
        for (int o = 16; o > 0; o >>= 1) {
            cv += __shfl_down_sync(0xFFFFFFFFu, cv, o);
            rv += __shfl_down_sync(0xFFFFFFFFu, rv, o);
            pv += __shfl_down_sync(0xFFFFFFFFu, pv, o);
        }
        if (lane == 0) { s_rc[wid] = cv; s_rr[wid] = rv; s_rp[wid] = pv; }
        __syncthreads();
        if (tid == 0) {
            float c = 0.0f, r = 0.0f;
            int p = 0;
            #pragma unroll
            for (int i = 0; i < APB / 32; i++) {
                c += s_rc[i]; r += s_rr[i]; p += s_rp[i];
            }
            g_cls_part[t] = c;
            g_reg_part[t] = r;
            g_pos_part[t] = p;
            __threadfence();
            const unsigned int tk = atomicAdd(&g_ticket, 1u);
            if (tk == (unsigned int)(NBLK - 1)) s_final = true;
        }
        __syncthreads();
    }

    // =================== finalize (the CTA that wrote the last tile) =======
    if (s_final) {
        __shared__ double f_c[B][APB / 32];
        __shared__ double f_r[B][APB / 32];
        __shared__ int    f_p[B][APB / 32];

        #pragma unroll
        for (int img = 0; img < B; img++) {
            double c = 0.0, r = 0.0;
            int p = 0;
            for (int i = tid; i < NTILES; i += APB) {
                const int idx = img * NTILES + i;
                c += (double)g_cls_part[idx];
                r += (double)g_reg_part[idx];
                p += g_pos_part[idx];
            }
            #pragma unroll
            for (int o = 16; o > 0; o >>= 1) {
                c += __shfl_down_sync(0xFFFFFFFFu, c, o);
                r += __shfl_down_sync(0xFFFFFFFFu, r, o);
                p += __shfl_down_sync(0xFFFFFFFFu, p, o);
            }
            if (lane == 0) { f_c[img][wid] = c; f_r[img][wid] = r; f_p[img][wid] = p; }
        }
        __syncthreads();
        if (tid == 0) {
            double cl = 0.0, rl = 0.0;
            #pragma unroll
            for (int img = 0; img < B; img++) {
                double c = 0.0, r = 0.0;
                int p = 0;
                #pragma unroll
                for (int i = 0; i < APB / 32; i++) {
                    c += f_c[img][i]; r += f_r[img][i]; p += f_p[img][i];
                }
                const double d = (p < 1) ? 1.0 : (double)p;
                cl += c / d;
                if (p > 0) rl += r / (4.0 * d);
            }
            out[0] = (float)(cl / (double)B);
            out[1] = (float)(rl / (double)B);
            g_ticket = 0;  // reset for the next graph replay
        }
    }
}

extern "C" void kernel_launch(void* const* d_in, const int* in_sizes, int n_in,
                              void* d_out, int out_size) {
    const float* cls = nullptr;
    const float* reg = nullptr;
    const float* anc = nullptr;
    const float* ann = nullptr;
    for (int i = 0; i < n_in; i++) {
        switch (in_sizes[i]) {
            case B * A * C:  cls = (const float*)d_in[i]; break;  // 64,000,000
            case B * A * 4:  reg = (const float*)d_in[i]; break;  //  3,200,000
            case A * 4:      anc = (const float*)d_in[i]; break;  //    400,000
            case B * M * 6:  ann = (const float*)d_in[i]; break;  //      1,536
            default: break;
        }
    }
    float* out = (float*)d_out;

    cudaFuncSetAttribute(fl_ring_kernel,
                         cudaFuncAttributeMaxDynamicSharedMemorySize, SMEM_DYN);
    fl_ring_kernel<<<GRID, APB, SMEM_DYN>>>(cls, reg, anc, ann, out);
}

// round 16
// speedup vs baseline: 1.1610x; 1.1313x over previous
#include <cuda_runtime.h>
#include <math.h>
#include <stdint.h>

// Problem constants
#define B 8
#define A 100000
#define M 32
#define C 80
#define APB 320                      // threads = anchors per tile (16*20)
#define NTILES ((A + APB - 1) / APB) // 313
#define NBLK (NTILES * B)            // 2504
#define V4PA (C / 4)                 // float4 per anchor = 20
#define CHA 40                       // anchors per chunk
#define CHF (CHA * C)                // 3200 floats per chunk
#define CHB (CHF * 4)                // 12800 bytes per chunk
#define CH4 (CHF / 4)                // 800 float4 per chunk
#define NSLOT 4                      // ring depth
#define SMEM_DYN (NSLOT * CHB)       // 51200 bytes (4-deep ring)

// mask weight for contributing anchors: -0.75 * ln(2)
#define NEGW (-0.5198603854199589f)

// Per-CTA partials + finalize ticket (device globals; no allocation allowed)
__device__ float g_cls_part[NBLK];
__device__ float g_reg_part[NBLK];
__device__ int   g_pos_part[NBLK];
__device__ unsigned int g_ticket = 0;

__device__ __forceinline__ uint32_t s2u(const void* p) {
    uint32_t r;
    asm("{ .reg .u64 t; cvta.to.shared.u64 t, %1; cvt.u32.u64 %0, t; }"
        : "=r"(r) : "l"(p));
    return r;
}
__device__ __forceinline__ void mbar_init(uint32_t mbar, uint32_t cnt) {
    asm volatile("mbarrier.init.shared.b64 [%0], %1;" :: "r"(mbar), "r"(cnt) : "memory");
}
__device__ __forceinline__ void mbar_expect_tx(uint32_t mbar, uint32_t bytes) {
    asm volatile("mbarrier.arrive.expect_tx.shared.b64 _, [%0], %1;"
                 :: "r"(mbar), "r"(bytes) : "memory");
}
__device__ __forceinline__ void bulk_g2s(uint32_t dst, const void* src,
                                         uint32_t bytes, uint32_t mbar) {
    asm volatile(
        "cp.async.bulk.shared::cta.global.mbarrier::complete_tx::bytes "
        "[%0], [%1], %2, [%3];"
        :: "r"(dst), "l"(src), "r"(bytes), "r"(mbar) : "memory");
}
__device__ __forceinline__ void fence_async_shared() {
    asm volatile("fence.proxy.async.shared::cta;" ::: "memory");
}
__device__ __forceinline__ void mbar_wait(uint32_t mbar, uint32_t parity) {
    asm volatile(
        "{\n\t"
        ".reg .pred P;\n\t"
        "WL_%=:\n\t"
        "mbarrier.try_wait.parity.acquire.cta.shared::cta.b64 P, [%0], %1, 0x989680;\n\t"
        "@P bra WD_%=;\n\t"
        "bra WL_%=;\n\t"
        "WD_%=:\n\t"
        "}"
        :: "r"(mbar), "r"(parity) : "memory");
}

__global__ __launch_bounds__(APB) void fl_ring4_kernel(
    const float* __restrict__ cls,      // [B, A, C]
    const float* __restrict__ reg,      // [B, A, 4]
    const float* __restrict__ anchors,  // [1, A, 4]
    const float* __restrict__ ann,      // [B, M, 6]
    float* __restrict__ out)            // [2]
{
    extern __shared__ __align__(16) float s_buf[];   // NSLOT x CHF floats

    __shared__ float4 s_box[M];
    __shared__ float2 s_misc[M];         // x = area_b, y = class id
    __shared__ float  s_mask[APB];       // NEGW if anchor contributes, else 0
    __shared__ float  s_rc[APB / 32];
    __shared__ float  s_rr[APB / 32];
    __shared__ int    s_rp[APB / 32];
    __shared__ bool   s_last;
    __shared__ __align__(8) unsigned long long s_mbar[NSLOT];

    const int b    = blockIdx.y;
    const int a0   = blockIdx.x * APB;
    const int tid  = threadIdx.x;
    const int wid  = tid >> 5;
    const int lane = tid & 31;
    const int blk  = b * NTILES + blockIdx.x;
    const int nA   = min(APB, A - a0);   // 320 or 160 (both multiples of 40)
    const int nch  = nA / CHA;           // 8 or 4

    const float* __restrict__ tile = cls + ((size_t)b * A + a0) * C;

    // init mbarriers + stage annotations
    if (tid < NSLOT) mbar_init(s2u(&s_mbar[tid]), 1);
    if (tid < M) {
        const float* ap = ann + (b * M + tid) * 6;
        float x1 = ap[0], y1 = ap[1], x2 = ap[2], y2 = ap[3];
        const float cl = ap[4];
        float area = (x2 - x1) * (y2 - y1);
        if (cl == -1.0f) {
            // Invalid GT: far-away box -> inter == 0 always, area 0 ->
            // identical classification/argmax behavior to reference's iou=-1.
            x1 = 3e9f; y1 = 3e9f; x2 = 3e9f; y2 = 3e9f; area = 0.0f;
        }
        s_box[tid]  = make_float4(x1, y1, x2, y2);
        s_misc[tid] = make_float2(area, cl);
    }
    __syncthreads();

    // prologue: fill the whole ring (4 x 12.8KB in flight) before phase 1
    if (tid == 0) {
        #pragma unroll
        for (int q = 0; q < NSLOT; q++) {
            const uint32_t mb = s2u(&s_mbar[q]);
            mbar_expect_tx(mb, CHB);
            bulk_g2s(s2u(&s_buf[q * CHF]), tile + q * CHF, CHB, mb);
        }
    }

    // ================= phase 1: IoU assignment (overlapped with copies) ====
    float cls_partial = 0.0f;
    float reg_partial = 0.0f;
    int   pos_cnt = 0;

    const int a = a0 + tid;
    if (a < A) {
        const float4 av = *reinterpret_cast<const float4*>(anchors + a * 4);
        const float ax1 = av.x, ay1 = av.y, ax2 = av.z, ay2 = av.w;
        const float aw = ax2 - ax1;
        const float ah = ay2 - ay1;
        const float area_a = aw * ah;

        // IoU argmax via cross-multiplication (no division; ua >= area_a > 0)
        float b_in = -1.0f, b_ua = 1.0f;
        int   bi = 0;
        #pragma unroll 8
        for (int j = 0; j < M; j++) {
            const float4 g  = s_box[j];
            const float2 mi = s_misc[j];
            const float iw = fminf(ax2, g.z) - fmaxf(ax1, g.x);
            const float ih = fminf(ay2, g.w) - fmaxf(ay1, g.y);
            const float inter = fmaxf(iw, 0.0f) * fmaxf(ih, 0.0f);
            const float ua = (area_a + mi.x) - inter;
            if (inter * b_ua > b_in * ua) { b_in = inter; b_ua = ua; bi = j; }
        }

        const bool pos = (b_in >= 0.5f * b_ua);
        const bool ign = (!pos) && (b_in >= 0.4f * b_ua);
        s_mask[tid] = ign ? 0.0f : NEGW;

        if (pos) {
            pos_cnt = 1;
            const float4 g = s_box[bi];

            // positive-class correction: remove exactly the unmasked sweep
            // term, add the reference positive term.
            const int cid = (int)s_misc[bi].y;
            const float p_raw = cls[((size_t)b * A + a) * C + cid];
            const float sweep_term =
                NEGW * (p_raw * p_raw * __log2f(1.0f - p_raw));
            const float pc = fminf(fmaxf(p_raw, 1e-4f), 1.0f - 1e-4f);
            const float qc = 1.0f - pc;
            cls_partial += 0.25f * qc * qc * (-__logf(pc)) - sweep_term;

            // regression loss (smooth L1)
            float gw = g.z - g.x;
            float gh = g.w - g.y;
            const float gcx = g.x + 0.5f * gw;
            const float gcy = g.y + 0.5f * gh;
            gw = fmaxf(gw, 1.0f);
            gh = fmaxf(gh, 1.0f);
            const float acx = ax1 + 0.5f * aw;
            const float acy = ay1 + 0.5f * ah;
            const float t0 = ((gcx - acx) / aw) * 10.0f;
            const float t1 = ((gcy - acy) / ah) * 10.0f;
            const float t2 = __logf(gw / aw) * 5.0f;
            const float t3 = __logf(gh / ah) * 5.0f;
            const float4 r = *reinterpret_cast<const float4*>(reg + ((size_t)b * A + a) * 4);
            const float d0 = fabsf(t0 - r.x);
            const float d1 = fabsf(t1 - r.y);
            const float d2 = fabsf(t2 - r.z);
            const float d3 = fabsf(t3 - r.w);
            const float th = 1.0f / 9.0f;
            const float c2 = 0.5f / 9.0f;
            reg_partial  = (d0 <= th) ? 4.5f * d0 * d0 : d0 - c2;
            reg_partial += (d1 <= th) ? 4.5f * d1 * d1 : d1 - c2;
            reg_partial += (d2 <= th) ? 4.5f * d2 * d2 : d2 - c2;
            reg_partial += (d3 <= th) ? 4.5f * d3 * d3 : d3 - c2;
        }
    } else {
        s_mask[tid] = 0.0f;
    }
    __syncthreads();   // masks visible to all consumers

    // ================= phase 2: 4-deep ring consume + refill ================
    // While consuming chunk q, chunks q+1..q+3 (38.4KB) stay in flight per
    // CTA (~153KB/SM at 4 CTAs/SM); after the post-consume sync, slot q&3 is
    // immediately re-armed with chunk q+4.
    const int mbase = tid / 20;   // APB = 16*20
    float acc0 = 0.f, acc1 = 0.f;

    for (int q = 0; q < nch; q++) {
        const int slot = q & 3;
        mbar_wait(s2u(&s_mbar[slot]), (q >> 2) & 1);

        const float4* sb4 = reinterpret_cast<const float4*>(s_buf + slot * CHF);
        const int moff = q * CHA;   // anchor offset of this chunk in the tile

        // 800 float4 per chunk over 320 threads = 2.5 each:
        // tid -> anchor moff + mbase; tid+320 -> +16; tid+640 (tid<160) -> +32
        {
            const float4 v = sb4[tid];
            const float m = s_mask[moff + mbase];
            const float l0 = __log2f(1.0f - v.x);
            const float l1 = __log2f(1.0f - v.y);
            const float l2 = __log2f(1.0f - v.z);
            const float l3 = __log2f(1.0f - v.w);
            const float s = fmaf(v.x * v.x, l0, fmaf(v.y * v.y, l1,
                            fmaf(v.z * v.z, l2, (v.w * v.w) * l3)));
            acc0 = fmaf(m, s, acc0);
        }
        {
            const float4 v = sb4[tid + 320];
            const float m = s_mask[moff + mbase + 16];
            const float l0 = __log2f(1.0f - v.x);
            const float l1 = __log2f(1.0f - v.y);
            const float l2 = __log2f(1.0f - v.z);
            const float l3 = __log2f(1.0f - v.w);
            const float s = fmaf(v.x * v.x, l0, fmaf(v.y * v.y, l1,
                            fmaf(v.z * v.z, l2, (v.w * v.w) * l3)));
            acc1 = fmaf(m, s, acc1);
        }
        if (tid < 160) {
            const float4 v = sb4[tid + 640];
            const float m = s_mask[moff + mbase + 32];
            const float l0 = __log2f(1.0f - v.x);
            const float l1 = __log2f(1.0f - v.y);
            const float l2 = __log2f(1.0f - v.z);
            const float l3 = __log2f(1.0f - v.w);
            const float s = fmaf(v.x * v.x, l0, fmaf(v.y * v.y, l1,
                            fmaf(v.z * v.z, l2, (v.w * v.w) * l3)));
            acc0 = fmaf(m, s, acc0);
        }

        __syncthreads();   // all reads of this slot done
        if (q + NSLOT < nch) {
            if (tid == 0) {
                fence_async_shared();
                const uint32_t mb = s2u(&s_mbar[slot]);
                mbar_expect_tx(mb, CHB);
                bulk_g2s(s2u(&s_buf[slot * CHF]),
                         tile + (q + NSLOT) * CHF, CHB, mb);
            }
        }
    }
    cls_partial += acc0 + acc1;

    // Block reduction -> per-CTA partials
    float cv = cls_partial;
    float rv = reg_partial;
    int   pv = pos_cnt;
    #pragma unroll
    for (int o = 16; o > 0; o >>= 1) {
        cv += __shfl_down_sync(0xFFFFFFFFu, cv, o);
        rv += __shfl_down_sync(0xFFFFFFFFu, rv, o);
        pv += __shfl_down_sync(0xFFFFFFFFu, pv, o);
    }
    if (lane == 0) { s_rc[wid] = cv; s_rr[wid] = rv; s_rp[wid] = pv; }
    __syncthreads();

    if (tid == 0) {
        float c = 0.0f, r = 0.0f;
        int p = 0;
        #pragma unroll
        for (int i = 0; i < APB / 32; i++) { c += s_rc[i]; r += s_rr[i]; p += s_rp[i]; }
        g_cls_part[blk] = c;
        g_reg_part[blk] = r;
        g_pos_part[blk] = p;
        __threadfence();
        const unsigned int t = atomicAdd(&g_ticket, 1u);
        s_last = (t == (unsigned int)(NBLK - 1));
    }
    __syncthreads();

    // Last CTA reduces all per-CTA partials and writes the output.
    if (s_last) {
        __shared__ double f_c[B][APB / 32];
        __shared__ double f_r[B][APB / 32];
        __shared__ int    f_p[B][APB / 32];

        #pragma unroll
        for (int img = 0; img < B; img++) {
            double c = 0.0, r = 0.0;
            int p = 0;
            for (int i = tid; i < NTILES; i += APB) {
                const int idx = img * NTILES + i;
                c += (double)g_cls_part[idx];
                r += (double)g_reg_part[idx];
                p += g_pos_part[idx];
            }
            #pragma unroll
            for (int o = 16; o > 0; o >>= 1) {
                c += __shfl_down_sync(0xFFFFFFFFu, c, o);
                r += __shfl_down_sync(0xFFFFFFFFu, r, o);
                p += __shfl_down_sync(0xFFFFFFFFu, p, o);
            }
            if (lane == 0) { f_c[img][wid] = c; f_r[img][wid] = r; f_p[img][wid] = p; }
        }
        __syncthreads();
        if (tid == 0) {
            double cl = 0.0, rl = 0.0;
            #pragma unroll
            for (int img = 0; img < B; img++) {
                double c = 0.0, r = 0.0;
                int p = 0;
                #pragma unroll
                for (int i = 0; i < APB / 32; i++) {
                    c += f_c[img][i]; r += f_r[img][i]; p += f_p[img][i];
                }
                const double d = (p < 1) ? 1.0 : (double)p;
                cl += c / d;
                if (p > 0) rl += r / (4.0 * d);
            }
            out[0] = (float)(cl / (double)B);
            out[1] = (float)(rl / (double)B);
            g_ticket = 0;  // reset for the next graph replay
        }
    }
}

extern "C" void kernel_launch(void* const* d_in, const int* in_sizes, int n_in,
                              void* d_out, int out_size) {
    const float* cls = nullptr;
    const float* reg = nullptr;
    const float* anc = nullptr;
    const float* ann = nullptr;
    for (int i = 0; i < n_in; i++) {
        switch (in_sizes[i]) {
            case B * A * C:  cls = (const float*)d_in[i]; break;  // 64,000,000
            case B * A * 4:  reg = (const float*)d_in[i]; break;  //  3,200,000
            case A * 4:      anc = (const float*)d_in[i]; break;  //    400,000
            case B * M * 6:  ann = (const float*)d_in[i]; break;  //      1,536
            default: break;
        }
    }
    float* out = (float*)d_out;

    cudaFuncSetAttribute(fl_ring4_kernel,
                         cudaFuncAttributeMaxDynamicSharedMemorySize, SMEM_DYN);
    dim3 grid(NTILES, B);
    fl_ring4_kernel<<<grid, APB, SMEM_DYN>>>(cls, reg, anc, ann, out);
}